// round 1
// baseline (speedup 1.0000x reference)
#include <cuda_runtime.h>
#include <math.h>

#define D        2048
#define NEXP     64
#define TM       64
#define KC       64
#define NCHUNK   (D / KC)        // 32
#define THREADS  256

// Scratch: normalized expert table, TRANSPOSED to [k][e] so GEMM B-chunks are
// contiguous rows, plus per-expert sums of the normalized rows (≈0, kept for
// exact math parity with the reference).
__device__ float g_enorm_t[D * NEXP];
__device__ float g_esum[NEXP];

__device__ __forceinline__ float block_reduce256(float v, float* red) {
    int tid = threadIdx.x;
    __syncthreads();                 // protect red[] reuse across calls
    #pragma unroll
    for (int o = 16; o > 0; o >>= 1) v += __shfl_xor_sync(0xffffffffu, v, o);
    if ((tid & 31) == 0) red[tid >> 5] = v;
    __syncthreads();
    float r = (tid < 8) ? red[tid] : 0.f;
    #pragma unroll
    for (int o = 4; o > 0; o >>= 1) r += __shfl_xor_sync(0xffffffffu, r, o);
    if (tid == 0) red[0] = r;
    __syncthreads();
    return red[0];
}

__global__ __launch_bounds__(THREADS) void normalize_experts(const float* __restrict__ emb) {
    __shared__ float red[8];
    const int e   = blockIdx.x;
    const int tid = threadIdx.x;
    const float4* row = reinterpret_cast<const float4*>(emb + e * D);

    float4 v0 = row[tid];
    float4 v1 = row[tid + 256];

    float s  = v0.x + v0.y + v0.z + v0.w + v1.x + v1.y + v1.z + v1.w;
    float sq = v0.x*v0.x + v0.y*v0.y + v0.z*v0.z + v0.w*v0.w
             + v1.x*v1.x + v1.y*v1.y + v1.z*v1.z + v1.w*v1.w;

    s  = block_reduce256(s,  red);
    sq = block_reduce256(sq, red);

    const float mu   = s * (1.f / D);
    const float var  = sq * (1.f / D) - mu * mu;
    const float rstd = rsqrtf(var + 1e-5f);

    float nv[8];
    nv[0] = (v0.x - mu) * rstd; nv[1] = (v0.y - mu) * rstd;
    nv[2] = (v0.z - mu) * rstd; nv[3] = (v0.w - mu) * rstd;
    nv[4] = (v1.x - mu) * rstd; nv[5] = (v1.y - mu) * rstd;
    nv[6] = (v1.z - mu) * rstd; nv[7] = (v1.w - mu) * rstd;

    float ls = 0.f;
    #pragma unroll
    for (int i = 0; i < 4; i++) {
        int k0 = tid * 4 + i;
        int k1 = 1024 + tid * 4 + i;
        g_enorm_t[k0 * NEXP + e] = nv[i];
        g_enorm_t[k1 * NEXP + e] = nv[4 + i];
        ls += nv[i] + nv[4 + i];
    }
    ls = block_reduce256(ls, red);
    if (tid == 0) g_esum[e] = ls;
}

__global__ __launch_bounds__(THREADS) void router_kernel(
    const float* __restrict__ x, float* __restrict__ out, int half)
{
    __shared__ float As[TM][KC];          // [token][k]
    __shared__ float Bs[KC][NEXP];        // [k][expert]
    __shared__ float sim[TM][NEXP + 1];   // +1 pad: conflict-free row scans
    __shared__ float smu[TM], srstd[TM], sesum[NEXP];

    const int tid    = threadIdx.x;
    const int m0     = blockIdx.x * TM;
    const int row    = tid >> 2;          // 0..63 : token row (A) / k row (B)
    const int fourth = tid & 3;
    const int tx     = tid & 15;          // expert group  -> e0 = tx*4
    const int ty     = tid >> 4;          // token group   -> m  = ty*4

    if (tid < NEXP) sesum[tid] = g_esum[tid];

    const float* arow = x + (size_t)(m0 + row) * D;

    float acc[4][4] = {};
    float s = 0.f, sq = 0.f;

    float4 abuf[4], bbuf[4];
    #pragma unroll
    for (int j = 0; j < 4; j++) {
        int f4 = fourth + 4 * j;
        abuf[j] = *reinterpret_cast<const float4*>(arow + f4 * 4);
        bbuf[j] = *reinterpret_cast<const float4*>(g_enorm_t + row * NEXP + f4 * 4);
    }

    for (int c = 0; c < NCHUNK; c++) {
        __syncthreads();
        #pragma unroll
        for (int j = 0; j < 4; j++) {
            int f4 = fourth + 4 * j;
            *reinterpret_cast<float4*>(&As[row][f4 * 4]) = abuf[j];
            *reinterpret_cast<float4*>(&Bs[row][f4 * 4]) = bbuf[j];
            s  += abuf[j].x + abuf[j].y + abuf[j].z + abuf[j].w;
            sq += abuf[j].x*abuf[j].x + abuf[j].y*abuf[j].y
                + abuf[j].z*abuf[j].z + abuf[j].w*abuf[j].w;
        }
        __syncthreads();

        if (c + 1 < NCHUNK) {
            int k0 = (c + 1) * KC;
            #pragma unroll
            for (int j = 0; j < 4; j++) {
                int f4 = fourth + 4 * j;
                abuf[j] = *reinterpret_cast<const float4*>(arow + k0 + f4 * 4);
                bbuf[j] = *reinterpret_cast<const float4*>(
                              g_enorm_t + (size_t)(k0 + row) * NEXP + f4 * 4);
            }
        }

        #pragma unroll 16
        for (int kk = 0; kk < KC; kk++) {
            float4 b = *reinterpret_cast<const float4*>(&Bs[kk][tx * 4]);
            float a0 = As[ty * 4 + 0][kk];
            float a1 = As[ty * 4 + 1][kk];
            float a2 = As[ty * 4 + 2][kk];
            float a3 = As[ty * 4 + 3][kk];
            acc[0][0] += a0 * b.x; acc[0][1] += a0 * b.y; acc[0][2] += a0 * b.z; acc[0][3] += a0 * b.w;
            acc[1][0] += a1 * b.x; acc[1][1] += a1 * b.y; acc[1][2] += a1 * b.z; acc[1][3] += a1 * b.w;
            acc[2][0] += a2 * b.x; acc[2][1] += a2 * b.y; acc[2][2] += a2 * b.z; acc[2][3] += a2 * b.w;
            acc[3][0] += a3 * b.x; acc[3][1] += a3 * b.y; acc[3][2] += a3 * b.z; acc[3][3] += a3 * b.w;
        }
    }

    // token stats: each thread summed its quarter-row; reduce over the 4 lanes
    s  += __shfl_xor_sync(0xffffffffu, s, 1);
    s  += __shfl_xor_sync(0xffffffffu, s, 2);
    sq += __shfl_xor_sync(0xffffffffu, sq, 1);
    sq += __shfl_xor_sync(0xffffffffu, sq, 2);
    if (fourth == 0) {
        float mu  = s * (1.f / D);
        float var = sq * (1.f / D) - mu * mu;
        smu[row]   = mu;
        srstd[row] = rsqrtf(var + 1e-5f);
    }
    __syncthreads();

    #pragma unroll
    for (int i = 0; i < 4; i++) {
        int m = ty * 4 + i;
        float mu = smu[m], rs = srstd[m];
        #pragma unroll
        for (int j = 0; j < 4; j++) {
            int e = tx * 4 + j;
            sim[m][e] = rs * (acc[i][j] - mu * sesum[e]);
        }
    }
    __syncthreads();

    if (tid < TM) {
        float v1 = -1e30f, v2 = -1e30f;
        int   i1 = 0,      i2 = 0;
        #pragma unroll 8
        for (int e = 0; e < NEXP; e++) {
            float v = sim[tid][e];
            if (v > v1)      { v2 = v1; i2 = i1; v1 = v; i1 = e; }
            else if (v > v2) { v2 = v; i2 = e; }
        }
        const float invt = 1.f / 45.254833995939045f;  // 1/sqrt(2048)
        float e2 = __expf((v2 - v1) * invt);
        float g1 = 1.f / (1.f + e2);
        float g2 = e2 / (1.f + e2);

        int gt = m0 + tid;
        out[2 * gt + 0]        = (float)i1;
        out[2 * gt + 1]        = (float)i2;
        out[half + 2 * gt + 0] = g1;
        out[half + 2 * gt + 1] = g2;
    }
}

extern "C" void kernel_launch(void* const* d_in, const int* in_sizes, int n_in,
                              void* d_out, int out_size) {
    const float* x   = (const float*)d_in[0];   // [4,4096,2048] fp32
    const float* emb = (const float*)d_in[1];   // [64,2048]    fp32
    float* out = (float*)d_out;

    int ntok = in_sizes[0] / D;                 // 16384
    normalize_experts<<<NEXP, THREADS>>>(emb);
    router_kernel<<<ntok / TM, THREADS>>>(x, out, out_size / 2);
}